// round 13
// baseline (speedup 1.0000x reference)
#include <cuda_runtime.h>

#define SDIM    4096
#define HDIM    16
#define PDIM    64
#define NDIM    64
#define LCHUNK  64
#define NCHUNK  64
#define NBH     128
#define THRESH  9.0f      // truncation ~5e-5 rel (measured) << 1e-3 budget
#define THREADS 512
#define WIN     256       // A-scan window: 4 chunks

// Dynamic smem (floats): xs[3][64][64], bs[3][64][64], ws[WIN]
#define XS_SLOT 4096
#define BS_SLOT 4096
#define XS_OFF  0
#define BS_OFF  (3 * XS_SLOT)
#define WS_OFF  (BS_OFF + 3 * BS_SLOT)      // 24576
#define SMEM_BYTES ((WS_OFF + WIN) * 4)     // 99328 B

__device__ __forceinline__ void ffma2(unsigned long long& d,
                                      unsigned long long a,
                                      unsigned long long b) {
    asm("fma.rn.f32x2 %0, %1, %2, %0;" : "+l"(d) : "l"(a), "l"(b));
}
__device__ __forceinline__ void fadd2(unsigned long long& d, unsigned long long a) {
    asm("add.rn.f32x2 %0, %0, %1;" : "+l"(d) : "l"(a));
}
__device__ __forceinline__ unsigned long long pack2(float lo, float hi) {
    unsigned long long r;
    asm("mov.b64 %0, {%1, %2};" : "=l"(r) : "f"(lo), "f"(hi));
    return r;
}
__device__ __forceinline__ void unpack2(unsigned long long v, float& lo, float& hi) {
    asm("mov.b64 {%0, %1}, %2;" : "=f"(lo), "=f"(hi) : "l"(v));
}
__device__ __forceinline__ void cp16(float* smem_dst, const float4* gmem_src) {
    unsigned sptr = (unsigned)__cvta_generic_to_shared(smem_dst);
    asm volatile("cp.async.cg.shared.global [%0], [%1], 16;"
                 :: "r"(sptr), "l"(gmem_src) : "memory");
}
#define CP_COMMIT() asm volatile("cp.async.commit_group;" ::: "memory")
#define CP_WAIT(n)  asm volatile("cp.async.wait_group %0;" :: "n"(n) : "memory")

union F4U2 { float4 f4; unsigned long long u2[2]; };

__device__ __forceinline__ void load_chunk(float* sm, int slot, int chunk,
                                           int b, int h, int tid,
                                           const float4* X4, const float4* B4) {
    const long tbase = (long)(b * SDIM + chunk * LCHUNK) * HDIM + h;
    float* xsl = sm + XS_OFF + slot * XS_SLOT;
    float* bsl = sm + BS_OFF + slot * BS_SLOT;
    #pragma unroll
    for (int k = 0; k < 2; k++) {
        const int i   = k * THREADS + tid;   // 0..1023
        const int row = i >> 4;
        const int col = i & 15;
        const long g  = (tbase + (long)row * HDIM) * 16 + col;
        cp16(xsl + row * 64 + col * 4, X4 + g);
        cp16(bsl + row * 64 + col * 4, B4 + g);
    }
}

// Scale X tile in place; reads exactly this thread's own cp.async data.
__device__ __forceinline__ void scale_chunk(float* sm, int slot, int wsbase,
                                            int tid) {
    const float* ws = sm + WS_OFF;
    float* xsl = sm + XS_OFF + slot * XS_SLOT;
    #pragma unroll
    for (int k = 0; k < 2; k++) {
        const int i   = k * THREADS + tid;
        const int row = i >> 4;
        const int col = i & 15;
        const float w = ws[wsbase + row];
        float4 v = *(const float4*)&xsl[row * 64 + col * 4];
        v.x *= w; v.y *= w; v.z *= w; v.w *= w;
        *(float4*)&xsl[row * 64 + col * 4] = v;
    }
}

// 4p x 4n register tile over this l-group's 32 rows, software-pipelined.
__device__ __forceinline__ void compute_chunk(const float* sm, int slot,
                                              int lh, int p0, int n0,
                                              unsigned long long acc[2][4]) {
    const float* xsl = sm + XS_OFF + slot * XS_SLOT + lh * 32 * 64 + p0;
    const float* bsl = sm + BS_OFF + slot * BS_SLOT + lh * 32 * 64 + n0;
    F4U2 xa;   float4 bv;
    xa.f4 = *(const float4*)xsl;
    bv    = *(const float4*)bsl;
    #pragma unroll 8
    for (int l = 0; l < 32; l++) {
        const unsigned long long b0 = pack2(bv.x, bv.x);
        const unsigned long long b1 = pack2(bv.y, bv.y);
        const unsigned long long b2 = pack2(bv.z, bv.z);
        const unsigned long long b3 = pack2(bv.w, bv.w);
        const F4U2 xc = xa;
        if (l < 31) {
            xa.f4 = *(const float4*)(xsl + (l + 1) * 64);
            bv    = *(const float4*)(bsl + (l + 1) * 64);
        }
        ffma2(acc[0][0], xc.u2[0], b0);
        ffma2(acc[0][1], xc.u2[0], b1);
        ffma2(acc[0][2], xc.u2[0], b2);
        ffma2(acc[0][3], xc.u2[0], b3);
        ffma2(acc[1][0], xc.u2[1], b0);
        ffma2(acc[1][1], xc.u2[1], b1);
        ffma2(acc[1][2], xc.u2[1], b2);
        ffma2(acc[1][3], xc.u2[1], b3);
    }
}

// Scan one 256-t window: fills ws[0..255] (decay weights incl. suffix) and
// sUj[0..3] (suffix-after-chunk, incl. suffix). Returns window total.
// Contains barriers; ALL threads must call.
__device__ __forceinline__ float scan_window(float a, float suffix,
                                             float* ws, float* sUj,
                                             float* warpsum,
                                             int tid, int lane, int warp) {
    float sc = a;
    #pragma unroll
    for (int d = 1; d < 32; d <<= 1) {
        float o = __shfl_up_sync(0xffffffffu, sc, d);
        if (lane >= d) sc += o;
    }
    if (warp < 8 && lane == 31) warpsum[warp] = sc;
    __syncthreads();
    if (warp == 0 && lane < 8) {
        float v = warpsum[lane];
        #pragma unroll
        for (int d = 1; d < 8; d <<= 1) {
            float o = __shfl_up_sync(0x000000ffu, v, d);
            if (lane >= d) v += o;
        }
        warpsum[lane] = v;
    }
    __syncthreads();
    const float total = warpsum[7];
    if (tid < WIN) {
        const float off = (warp > 0) ? warpsum[warp - 1] : 0.0f;
        const float u = total - (sc + off) + suffix;   // sum of A after t
        ws[tid] = __expf(u);
        if ((tid & 63) == 63) sUj[tid >> 6] = u;       // suffix after chunk
    }
    __syncthreads();
    return total;
}

__global__ void __launch_bounds__(THREADS, 1)
fused_mamba_kernel(const float* __restrict__ X,
                   const float* __restrict__ A,
                   const float* __restrict__ B,
                   float* __restrict__ out) {
    extern __shared__ float sm[];
    float* ws = sm + WS_OFF;

    __shared__ float warpsum[8];
    __shared__ float sUj[4];

    const int bh   = blockIdx.x;
    const int b    = bh >> 4;
    const int h    = bh & 15;
    const int tid  = threadIdx.x;
    const int lane = tid & 31;
    const int warp = tid >> 5;
    const int lh   = tid >> 8;          // l-half group (0/1)
    const int r    = tid & 255;
    const int p0   = (r >> 4) << 2;     // 4 p-values
    const int n0   = (r & 15) << 2;     // 4 n-values

    const float4* X4 = (const float4*)X;
    const float4* B4 = (const float4*)B;
    const float*  Ab = A + (long)b * SDIM * HDIM + h;

    // ---- Issue first A-window loads FIRST (long-latency, uncoalesced) -----
    int winStart = SDIM - WIN;          // 3840: chunks 60..63
    float a_pre = (tid < WIN) ? Ab[(winStart + tid) * HDIM] : 0.0f;

    // ---- Speculative prefetch: chunk 63 (group 1), chunk 62 (group 2) -----
    load_chunk(sm, 2, 63, b, h, tid, X4, B4);  CP_COMMIT();
    load_chunk(sm, 1, 62, b, h, tid, X4, B4);  CP_COMMIT();

    // ---- Window 0 scan ------------------------------------------------------
    float total = scan_window(a_pre, 0.0f, ws, sUj, warpsum, tid, lane, warp);

    const bool act61 = sUj[1] > -THRESH;       // ~5% of blocks
    const bool act62 = sUj[2] > -THRESH;       // ~always
    if (act61) { load_chunk(sm, 0, 61, b, h, tid, X4, B4); CP_COMMIT(); }

    unsigned long long acc[2][4];
    #pragma unroll
    for (int i = 0; i < 2; i++)
        #pragma unroll
        for (int n = 0; n < 4; n++) acc[i][n] = 0ull;

    // ---- Chunk 63 (always active) ------------------------------------------
    if (act61) CP_WAIT(2); else CP_WAIT(1);
    scale_chunk(sm, 2, 192, tid);
    __syncthreads();
    compute_chunk(sm, 2, lh, p0, n0, acc);

    // ---- Chunk 62 ------------------------------------------------------------
    if (act61) CP_WAIT(1); else CP_WAIT(0);
    if (act62) {
        scale_chunk(sm, 1, 128, tid);
        __syncthreads();
        compute_chunk(sm, 1, lh, p0, n0, acc);
    }

    // ---- Chunk 61 (demand-issued) --------------------------------------------
    if (act61) {
        CP_WAIT(0);
        scale_chunk(sm, 0, 64, tid);
        __syncthreads();
        compute_chunk(sm, 0, lh, p0, n0, acc);
    }

    // ---- Chunk 60 (same window; ~never) --------------------------------------
    if (sUj[0] > -THRESH) {
        __syncthreads();                // slot 0 free (compute 61 done by all)
        load_chunk(sm, 0, 60, b, h, tid, X4, B4); CP_COMMIT(); CP_WAIT(0);
        scale_chunk(sm, 0, 0, tid);
        __syncthreads();
        compute_chunk(sm, 0, lh, p0, n0, acc);
    }

    // ---- Earlier windows (probability ~0; correctness path) ------------------
    float suffix = total;
    winStart -= WIN;
    while (suffix > -THRESH && winStart >= 0) {
        float a = (tid < WIN) ? Ab[(winStart + tid) * HDIM] : 0.0f;
        const float wt = scan_window(a, suffix, ws, sUj, warpsum, tid, lane, warp);
        for (int jj = 3; jj >= 0; jj--) {
            if (sUj[jj] > -THRESH) {
                const int c = (winStart >> 6) + jj;
                const int slot = c % 3;
                __syncthreads();        // slot reuse vs prior compute
                load_chunk(sm, slot, c, b, h, tid, X4, B4); CP_COMMIT(); CP_WAIT(0);
                scale_chunk(sm, slot, jj * 64, tid);
                __syncthreads();
                compute_chunk(sm, slot, lh, p0, n0, acc);
            }
        }
        suffix += wt;
        winStart -= WIN;
    }

    // ---- Cross-group reduction (group1 -> smem, group0 adds) -----------------
    __syncthreads();
    unsigned long long* buf = (unsigned long long*)sm;   // reuse xs region
    if (lh == 1) {
        #pragma unroll
        for (int q = 0; q < 8; q++)
            buf[q * 256 + r] = acc[q >> 2][q & 3];
    }
    __syncthreads();
    if (lh == 0) {
        #pragma unroll
        for (int q = 0; q < 8; q++)
            fadd2(acc[q >> 2][q & 3], buf[q * 256 + r]);

        // ---- Write out[bh, p, n] ---------------------------------------------
        float4* out4 = (float4*)out + (long)bh * PDIM * 16;
        #pragma unroll
        for (int pi = 0; pi < 2; pi++) {
            float4 vlo, vhi;
            unpack2(acc[pi][0], vlo.x, vhi.x);
            unpack2(acc[pi][1], vlo.y, vhi.y);
            unpack2(acc[pi][2], vlo.z, vhi.z);
            unpack2(acc[pi][3], vlo.w, vhi.w);
            out4[(p0 + 2 * pi)     * 16 + (n0 >> 2)] = vlo;
            out4[(p0 + 2 * pi + 1) * 16 + (n0 >> 2)] = vhi;
        }
    }
}

// ---------------------------------------------------------------------------
extern "C" void kernel_launch(void* const* d_in, const int* in_sizes, int n_in,
                              void* d_out, int out_size) {
    const float* X = (const float*)d_in[0];
    const float* A = (const float*)d_in[1];
    const float* B = (const float*)d_in[2];
    float* out = (float*)d_out;

    cudaFuncSetAttribute(fused_mamba_kernel,
                         cudaFuncAttributeMaxDynamicSharedMemorySize,
                         SMEM_BYTES);
    fused_mamba_kernel<<<NBH, THREADS, SMEM_BYTES>>>(X, A, B, out);
}

// round 14
// speedup vs baseline: 1.0226x; 1.0226x over previous
#include <cuda_runtime.h>

#define SDIM    4096
#define HDIM    16
#define PDIM    64
#define NDIM    64
#define LCHUNK  64
#define NCHUNK  64
#define NBH     128
#define THRESH  9.0f      // truncation ~5e-5 rel (measured) << 1e-3 budget
#define THREADS 256
#define PHALF   32        // p-columns per block
#define WIN     256       // A-scan window: 4 chunks

// Dynamic smem (floats): xs[3][64][32], bs[3][64][64], ws[WIN]
#define XS_SLOT 2048
#define BS_SLOT 4096
#define XS_OFF  0
#define BS_OFF  (3 * XS_SLOT)               // 6144
#define WS_OFF  (BS_OFF + 3 * BS_SLOT)      // 18432
#define SMEM_BYTES ((WS_OFF + WIN) * 4)     // 74752 B

__device__ __forceinline__ void ffma2(unsigned long long& d,
                                      unsigned long long a,
                                      unsigned long long b) {
    asm("fma.rn.f32x2 %0, %1, %2, %0;" : "+l"(d) : "l"(a), "l"(b));
}
__device__ __forceinline__ void fadd2(unsigned long long& d, unsigned long long a) {
    asm("add.rn.f32x2 %0, %0, %1;" : "+l"(d) : "l"(a));
}
__device__ __forceinline__ unsigned long long pack2(float lo, float hi) {
    unsigned long long r;
    asm("mov.b64 %0, {%1, %2};" : "=l"(r) : "f"(lo), "f"(hi));
    return r;
}
__device__ __forceinline__ void unpack2(unsigned long long v, float& lo, float& hi) {
    asm("mov.b64 {%0, %1}, %2;" : "=f"(lo), "=f"(hi) : "l"(v));
}
__device__ __forceinline__ void cp16(float* smem_dst, const float4* gmem_src) {
    unsigned sptr = (unsigned)__cvta_generic_to_shared(smem_dst);
    asm volatile("cp.async.cg.shared.global [%0], [%1], 16;"
                 :: "r"(sptr), "l"(gmem_src) : "memory");
}
#define CP_COMMIT() asm volatile("cp.async.commit_group;" ::: "memory")
#define CP_WAIT(n)  asm volatile("cp.async.wait_group %0;" :: "n"(n) : "memory")

union F4U2 { float4 f4; unsigned long long u2[2]; };

// Load one chunk: this block's X p-half + full B.
__device__ __forceinline__ void load_chunk(float* sm, int slot, int chunk,
                                           int b, int h, int ph, int tid,
                                           const float4* X4, const float4* B4) {
    const long tbase = (long)(b * SDIM + chunk * LCHUNK) * HDIM + h;
    float* xsl = sm + XS_OFF + slot * XS_SLOT;
    float* bsl = sm + BS_OFF + slot * BS_SLOT;
    #pragma unroll
    for (int k = 0; k < 2; k++) {            // X half: 512 float4
        const int i   = k * THREADS + tid;
        const int row = i >> 3;
        const int col = i & 7;
        cp16(xsl + row * PHALF + col * 4,
             X4 + (tbase + (long)row * HDIM) * 16 + ph * 8 + col);
    }
    #pragma unroll
    for (int k = 0; k < 4; k++) {            // B full: 1024 float4
        const int i   = k * THREADS + tid;
        const int row = i >> 4;
        const int col = i & 15;
        cp16(bsl + row * 64 + col * 4,
             B4 + (tbase + (long)row * HDIM) * 16 + col);
    }
}

// Scale X tile in place (reads exactly this thread's own cp.async data).
__device__ __forceinline__ void scale_chunk(float* sm, int slot, int wsbase,
                                            int tid) {
    const float* ws = sm + WS_OFF;
    float* xsl = sm + XS_OFF + slot * XS_SLOT;
    #pragma unroll
    for (int k = 0; k < 2; k++) {
        const int i   = k * THREADS + tid;
        const int row = i >> 3;
        const int col = i & 7;
        const float w = ws[wsbase + row];
        float4 v = *(const float4*)&xsl[row * PHALF + col * 4];
        v.x *= w; v.y *= w; v.z *= w; v.w *= w;
        *(float4*)&xsl[row * PHALF + col * 4] = v;
    }
}

// 4p x 4n register tile over this l-group's 32 rows, software-pipelined.
__device__ __forceinline__ void compute_chunk(const float* sm, int slot,
                                              int lh, int p0, int n0,
                                              unsigned long long acc[2][4]) {
    const float* xsl = sm + XS_OFF + slot * XS_SLOT + lh * 32 * PHALF + p0;
    const float* bsl = sm + BS_OFF + slot * BS_SLOT + lh * 32 * 64 + n0;
    F4U2 xa;   float4 bv;
    xa.f4 = *(const float4*)xsl;
    bv    = *(const float4*)bsl;
    #pragma unroll 8
    for (int l = 0; l < 32; l++) {
        const unsigned long long b0 = pack2(bv.x, bv.x);
        const unsigned long long b1 = pack2(bv.y, bv.y);
        const unsigned long long b2 = pack2(bv.z, bv.z);
        const unsigned long long b3 = pack2(bv.w, bv.w);
        const F4U2 xc = xa;
        if (l < 31) {
            xa.f4 = *(const float4*)(xsl + (l + 1) * PHALF);
            bv    = *(const float4*)(bsl + (l + 1) * 64);
        }
        ffma2(acc[0][0], xc.u2[0], b0);
        ffma2(acc[0][1], xc.u2[0], b1);
        ffma2(acc[0][2], xc.u2[0], b2);
        ffma2(acc[0][3], xc.u2[0], b3);
        ffma2(acc[1][0], xc.u2[1], b0);
        ffma2(acc[1][1], xc.u2[1], b1);
        ffma2(acc[1][2], xc.u2[1], b2);
        ffma2(acc[1][3], xc.u2[1], b3);
    }
}

// Scan one 256-t window (all 256 threads): fills ws[0..255] and sUj[0..3].
// Returns window total. Contains barriers; ALL threads must call.
__device__ __forceinline__ float scan_window(float a, float suffix,
                                             float* ws, float* sUj,
                                             float* warpsum,
                                             int tid, int lane, int warp) {
    float sc = a;
    #pragma unroll
    for (int d = 1; d < 32; d <<= 1) {
        float o = __shfl_up_sync(0xffffffffu, sc, d);
        if (lane >= d) sc += o;
    }
    if (lane == 31) warpsum[warp] = sc;
    __syncthreads();
    if (warp == 0 && lane < 8) {
        float v = warpsum[lane];
        #pragma unroll
        for (int d = 1; d < 8; d <<= 1) {
            float o = __shfl_up_sync(0x000000ffu, v, d);
            if (lane >= d) v += o;
        }
        warpsum[lane] = v;
    }
    __syncthreads();
    const float total = warpsum[7];
    {
        const float off = (warp > 0) ? warpsum[warp - 1] : 0.0f;
        const float u = total - (sc + off) + suffix;   // sum of A after t
        ws[tid] = __expf(u);
        if ((tid & 63) == 63) sUj[tid >> 6] = u;       // suffix after chunk
    }
    __syncthreads();
    return total;
}

__global__ void __launch_bounds__(THREADS, 2)
fused_mamba_kernel(const float* __restrict__ X,
                   const float* __restrict__ A,
                   const float* __restrict__ B,
                   float* __restrict__ out) {
    extern __shared__ float sm[];
    float* ws = sm + WS_OFF;

    __shared__ float warpsum[8];
    __shared__ float sUj[4];

    const int bh   = blockIdx.x;
    const int ph   = blockIdx.y;        // p-half (0/1)
    const int b    = bh >> 4;
    const int h    = bh & 15;
    const int tid  = threadIdx.x;
    const int lane = tid & 31;
    const int warp = tid >> 5;
    const int lh   = tid >> 7;          // l-half group (0/1)
    const int r    = tid & 127;
    const int p0   = (r >> 4) << 2;     // 4 p-values within half (0..28)
    const int n0   = (r & 15) << 2;     // 4 n-values (0..60)

    const float4* X4 = (const float4*)X;
    const float4* B4 = (const float4*)B;
    const float*  Ab = A + (long)b * SDIM * HDIM + h;

    // ---- Issue first A-window loads FIRST (long-latency, uncoalesced) -----
    int winStart = SDIM - WIN;          // 3840: chunks 60..63
    float a_pre = Ab[(winStart + tid) * HDIM];

    // ---- Speculative prefetch: chunk 63 then 62 ----------------------------
    load_chunk(sm, 2, 63, b, h, ph, tid, X4, B4);  CP_COMMIT();
    load_chunk(sm, 1, 62, b, h, ph, tid, X4, B4);  CP_COMMIT();

    // ---- Window 0 scan ------------------------------------------------------
    float total = scan_window(a_pre, 0.0f, ws, sUj, warpsum, tid, lane, warp);

    const bool act61 = sUj[1] > -THRESH;       // ~5% of blocks
    const bool act62 = sUj[2] > -THRESH;       // ~always
    if (act61) { load_chunk(sm, 0, 61, b, h, ph, tid, X4, B4); CP_COMMIT(); }

    unsigned long long acc[2][4];
    #pragma unroll
    for (int i = 0; i < 2; i++)
        #pragma unroll
        for (int n = 0; n < 4; n++) acc[i][n] = 0ull;

    // ---- Chunk 63 (always active) ------------------------------------------
    if (act61) CP_WAIT(2); else CP_WAIT(1);
    scale_chunk(sm, 2, 192, tid);
    __syncthreads();
    compute_chunk(sm, 2, lh, p0, n0, acc);

    // ---- Chunk 62 ------------------------------------------------------------
    if (act61) CP_WAIT(1); else CP_WAIT(0);
    if (act62) {
        scale_chunk(sm, 1, 128, tid);
        __syncthreads();
        compute_chunk(sm, 1, lh, p0, n0, acc);
    }

    // ---- Chunk 61 (demand-issued) --------------------------------------------
    if (act61) {
        CP_WAIT(0);
        scale_chunk(sm, 0, 64, tid);
        __syncthreads();
        compute_chunk(sm, 0, lh, p0, n0, acc);
    }

    // ---- Chunk 60 (same window; ~never) --------------------------------------
    if (sUj[0] > -THRESH) {
        __syncthreads();                // slot 0 free for reuse
        load_chunk(sm, 0, 60, b, h, ph, tid, X4, B4); CP_COMMIT(); CP_WAIT(0);
        scale_chunk(sm, 0, 0, tid);
        __syncthreads();
        compute_chunk(sm, 0, lh, p0, n0, acc);
    }

    // ---- Earlier windows (probability ~0; correctness path) ------------------
    float suffix = total;
    winStart -= WIN;
    while (suffix > -THRESH && winStart >= 0) {
        float a = Ab[(winStart + tid) * HDIM];
        const float wt = scan_window(a, suffix, ws, sUj, warpsum, tid, lane, warp);
        for (int jj = 3; jj >= 0; jj--) {
            if (sUj[jj] > -THRESH) {
                const int c = (winStart >> 6) + jj;
                const int slot = c % 3;
                __syncthreads();        // slot reuse vs prior compute
                load_chunk(sm, slot, c, b, h, ph, tid, X4, B4); CP_COMMIT(); CP_WAIT(0);
                scale_chunk(sm, slot, jj * 64, tid);
                __syncthreads();
                compute_chunk(sm, slot, lh, p0, n0, acc);
            }
        }
        suffix += wt;
        winStart -= WIN;
    }

    // ---- Cross-group reduction (group1 -> smem, group0 adds) -----------------
    __syncthreads();
    unsigned long long* buf = (unsigned long long*)sm;   // reuse xs region (8KB)
    if (lh == 1) {
        #pragma unroll
        for (int q = 0; q < 8; q++)
            buf[q * 128 + r] = acc[q >> 2][q & 3];
    }
    __syncthreads();
    if (lh == 0) {
        #pragma unroll
        for (int q = 0; q < 8; q++)
            fadd2(acc[q >> 2][q & 3], buf[q * 128 + r]);

        // ---- Write out[bh, ph*32 + p, n] -------------------------------------
        float4* out4 = (float4*)out + (long)bh * PDIM * 16 + ph * 32 * 16;
        #pragma unroll
        for (int pi = 0; pi < 2; pi++) {
            float4 vlo, vhi;
            unpack2(acc[pi][0], vlo.x, vhi.x);
            unpack2(acc[pi][1], vlo.y, vhi.y);
            unpack2(acc[pi][2], vlo.z, vhi.z);
            unpack2(acc[pi][3], vlo.w, vhi.w);
            out4[(p0 + 2 * pi)     * 16 + (n0 >> 2)] = vlo;
            out4[(p0 + 2 * pi + 1) * 16 + (n0 >> 2)] = vhi;
        }
    }
}

// ---------------------------------------------------------------------------
extern "C" void kernel_launch(void* const* d_in, const int* in_sizes, int n_in,
                              void* d_out, int out_size) {
    const float* X = (const float*)d_in[0];
    const float* A = (const float*)d_in[1];
    const float* B = (const float*)d_in[2];
    float* out = (float*)d_out;

    cudaFuncSetAttribute(fused_mamba_kernel,
                         cudaFuncAttributeMaxDynamicSharedMemorySize,
                         SMEM_BYTES);
    dim3 grid(NBH, 2);
    fused_mamba_kernel<<<grid, THREADS, SMEM_BYTES>>>(X, A, B, out);
}